// round 14
// baseline (speedup 1.0000x reference)
#include <cuda_runtime.h>
#include <cuda_fp16.h>
#include <cstdint>
#include <cstddef>

// Problem constants
#define B_   16
#define CIN  512
#define HW   4096
#define G_   8
#define EPSG 1e-5f
#define NPAIR 10            // triangle pairs of 128-blocks

// mainloop geometry
#define AS_LD 20
#define BS_LD 68
#define A_STG 10240
#define STG_U 18944
#define STG_S 20480
#define SMEM_U (4*STG_U)    // 75776 (k_u: 4-stage cp.async ring)
#define SMEM_P (2*STG_S)    // 40960 (k_prep S-path: 2-stage LDG/STS ring)

// merged prep grid layout
#define NP_S  160
#define NP_X  8192
#define NP_A  512
#define NP_M  4096
#define NP_C  4096
#define NP_TOT (NP_S + NP_X + NP_A + NP_M + NP_C)   // 17056

// ---------------- device scratch ----------------
__device__ __half g_A16[CIN*CIN];                // Wcomb fp16
__device__ __half g_M16[G_*CIN*CIN];             // Msym fp16 (4 MB)
__device__ __half g_C16[G_*CIN*CIN];             // Csym fp16 (4 MB)
__device__ __half g_S[(size_t)B_*NPAIR*128*128]; // Gram tiles fp16 (5.2 MB)
__device__ __half g_x16[(size_t)B_*CIN*HW];      // x fp16 (67 MB)
__device__ float  g_xsum[B_*CIN];
__device__ float  g_colsum[G_*CIN];
__device__ float  g_attp[B_*G_*NPAIR];
__device__ float  g_ssp[B_*G_*NPAIR];
__device__ float  g_scale[B_*CIN];
__device__ float  g_bias[B_*CIN];

// ---------------- PTX helpers ----------------
__device__ __forceinline__ uint32_t smem_u32(const void* p) {
    uint32_t a;
    asm("{ .reg .u64 t; cvta.to.shared.u64 t, %1; cvt.u32.u64 %0, t; }" : "=r"(a) : "l"(p));
    return a;
}
__device__ __forceinline__ void cpasync16(uint32_t dst, const void* src) {
    asm volatile("cp.async.cg.shared.global [%0], [%1], 16;" :: "r"(dst), "l"(src) : "memory");
}
#define CP_COMMIT()  asm volatile("cp.async.commit_group;" ::: "memory")
#define CP_WAIT(n)   asm volatile("cp.async.wait_group %0;" :: "n"(n) : "memory")

__device__ __forceinline__ void ldsm4(unsigned* r, uint32_t a) {
    asm volatile("ldmatrix.sync.aligned.m8n8.x4.shared.b16 {%0,%1,%2,%3}, [%4];"
        : "=r"(r[0]), "=r"(r[1]), "=r"(r[2]), "=r"(r[3]) : "r"(a));
}
__device__ __forceinline__ void ldsm4t(unsigned* r, uint32_t a) {
    asm volatile("ldmatrix.sync.aligned.m8n8.x4.trans.shared.b16 {%0,%1,%2,%3}, [%4];"
        : "=r"(r[0]), "=r"(r[1]), "=r"(r[2]), "=r"(r[3]) : "r"(a));
}
__device__ __forceinline__ void mma16(float* c, const unsigned* a, const unsigned* b) {
    asm volatile(
        "mma.sync.aligned.m16n8k16.row.col.f32.f16.f16.f32 "
        "{%0,%1,%2,%3}, {%4,%5,%6,%7}, {%8,%9}, {%0,%1,%2,%3};\n"
        : "+f"(c[0]), "+f"(c[1]), "+f"(c[2]), "+f"(c[3])
        : "r"(a[0]), "r"(a[1]), "r"(a[2]), "r"(a[3]), "r"(b[0]), "r"(b[1]));
}
__device__ __forceinline__ unsigned pk(float lo, float hi) {
    __half2 h = __floats2half2_rn(lo, hi);
    return *(unsigned*)&h;
}
__device__ __forceinline__ float wred(float v) {
#pragma unroll
    for (int o = 16; o; o >>= 1) v += __shfl_down_sync(0xffffffffu, v, o);
    return v;
}

// ---------------- K1: merged prep + S tiles ----------------
__global__ void __launch_bounds__(256, 2)
k_prep(const float* __restrict__ x,  const float* __restrict__ Wt,
       const float* __restrict__ Wz, const float* __restrict__ Wp,
       const float* __restrict__ Wg) {
    extern __shared__ char smem[];
    const int cta = blockIdx.x;
    const int tid = threadIdx.x;
    __shared__ float sWz[64*32];     // prepC
    __shared__ float sQ[32*33];
    __shared__ float sV[32];
    __shared__ float wz[32];         // prepA

    if (cta < NP_S) {
        // ===== S-path: S = X[chi] @ X[chj]^T (fp32 source, in-register convert) =====
        const uint32_t sb = smem_u32(smem);
        const int lane = tid & 31, warp = tid >> 5;
        const int wm = warp >> 1, wn = warp & 1;
        const int lr = lane >> 2, lc2 = (lane & 3)*2;
        const int pr = cta % NPAIR, b = cta / NPAIR;
        int ib = 0, rem = pr;
        while (rem > ib) { rem -= (ib + 1); ib++; }
        const int jb = rem;
        const int chi = ib*128, chj = jb*128;

        const int row = tid >> 1, ah = tid & 1;
        const float* isrc = x + ((size_t)b*CIN + chi + row)*HW + ah*16;
        const float* jsrc = x + ((size_t)b*CIN + chj + row)*HW + ah*16;
        const uint32_t off_i = row*80 + ah*32;
        const uint32_t off_j = A_STG + row*80 + ah*32;

        uint4 ti[2], tj[2];
        auto ldcv = [&](int s) {
#pragma unroll
            for (int h = 0; h < 2; h++) {
                float4 a0 = *(const float4*)(isrc + s*32 + h*8);
                float4 a1 = *(const float4*)(isrc + s*32 + h*8 + 4);
                ti[h].x = pk(a0.x, a0.y); ti[h].y = pk(a0.z, a0.w);
                ti[h].z = pk(a1.x, a1.y); ti[h].w = pk(a1.z, a1.w);
                float4 b0 = *(const float4*)(jsrc + s*32 + h*8);
                float4 b1 = *(const float4*)(jsrc + s*32 + h*8 + 4);
                tj[h].x = pk(b0.x, b0.y); tj[h].y = pk(b0.z, b0.w);
                tj[h].z = pk(b1.x, b1.y); tj[h].w = pk(b1.z, b1.w);
            }
        };
        auto sts = [&](int buf) {
            *(uint4*)(smem + buf*STG_S + off_i)      = ti[0];
            *(uint4*)(smem + buf*STG_S + off_i + 16) = ti[1];
            *(uint4*)(smem + buf*STG_S + off_j)      = tj[0];
            *(uint4*)(smem + buf*STG_S + off_j + 16) = tj[1];
        };

        const int l15 = lane & 15, lk = (lane >> 4) * 16;

        float acc[2][8][4];
#pragma unroll
        for (int mt = 0; mt < 2; mt++)
#pragma unroll
            for (int nt = 0; nt < 8; nt++)
#pragma unroll
                for (int i = 0; i < 4; i++) acc[mt][nt][i] = 0.f;

        ldcv(0);
        sts(0);
        for (int s = 0; s < 128; s++) {
            if (s + 1 < 128) ldcv(s + 1);
            __syncthreads();
            const uint32_t xi = sb + (s & 1)*STG_S;
            const uint32_t xj = xi + A_STG;
#pragma unroll
            for (int ks = 0; ks < 2; ks++) {
                unsigned af[2][4], bf[4][4];
#pragma unroll
                for (int mt = 0; mt < 2; mt++)
                    ldsm4(af[mt], xi + (wm*32 + mt*16 + l15)*80 + ks*32 + lk);
#pragma unroll
                for (int ng = 0; ng < 4; ng++)
                    ldsm4(bf[ng], xj + (wn*64 + ng*16 + l15)*80 + ks*32 + lk);
#pragma unroll
                for (int ng = 0; ng < 4; ng++) {
                    unsigned blo[2] = { bf[ng][0], bf[ng][2] };
                    unsigned bhi[2] = { bf[ng][1], bf[ng][3] };
#pragma unroll
                    for (int mt = 0; mt < 2; mt++) {
                        mma16(acc[mt][2*ng],     af[mt], blo);
                        mma16(acc[mt][2*ng + 1], af[mt], bhi);
                    }
                }
            }
            __syncthreads();
            if (s + 1 < 128) sts((s + 1) & 1);
        }

        __half* sdst = g_S + ((size_t)(b*NPAIR + pr) << 14);
#pragma unroll
        for (int mt = 0; mt < 2; mt++)
#pragma unroll
            for (int nt = 0; nt < 8; nt++)
#pragma unroll
                for (int i2 = 0; i2 < 2; i2++) {
                    int r = wm*32 + mt*16 + lr + i2*8;
                    int c = wn*64 + nt*8 + lc2;
                    *(__half2*)&sdst[r*128 + c] =
                        __floats2half2_rn(acc[mt][nt][i2*2], acc[mt][nt][i2*2 + 1]);
                }
    } else if (cta < NP_S + NP_X) {
        // ===== prepX: one (b,c) row -> fp16 + row sum =====
        const int rown = cta - NP_S;
        __shared__ float sb2[8];
        const float4* src = (const float4*)(x + (size_t)rown*HW);
        __half2* dst = (__half2*)(g_x16 + (size_t)rown*HW);
        float s = 0.f;
#pragma unroll
        for (int q = 0; q < 4; q++) {
            int i = q*256 + tid;
            float4 v = src[i];
            dst[2*i]     = __floats2half2_rn(v.x, v.y);
            dst[2*i + 1] = __floats2half2_rn(v.z, v.w);
            s += v.x + v.y + v.z + v.w;
        }
        s = wred(s);
        if ((tid & 31) == 0) sb2[tid >> 5] = s;
        __syncthreads();
        if (tid == 0) {
            float a = 0.f;
#pragma unroll
            for (int w2 = 0; w2 < 8; w2++) a += sb2[w2];
            g_xsum[rown] = a;
        }
    } else if (cta < NP_S + NP_X + NP_A) {
        // ===== prepA: one Wcomb row =====
        const int r = cta - NP_S - NP_X;
        const int g = r >> 6, o = r & 63;
        if (tid < 32) wz[tid] = Wz[(size_t)(g*64 + o)*32 + tid];
        __syncthreads();
#pragma unroll
        for (int q = 0; q < 2; q++) {
            int i = tid + q*256;
            float a = 0.f;
#pragma unroll 8
            for (int c = 0; c < 32; c++)
                a += wz[c] * Wt[(size_t)(g*32 + c)*CIN + i];
            g_A16[(size_t)r*CIN + i] = __float2half(a);
        }
    } else if (cta < NP_S + NP_X + NP_A + NP_M) {
        // ===== prepM: one (g,i) row of Msym = 0.5(Wp^T Wg + Wg^T Wp) =====
        const int idx = cta - NP_S - NP_X - NP_A;
        const int g = idx >> 9, i = idx & 511;
        float m0 = 0.f, m1 = 0.f;
#pragma unroll 4
        for (int c = 0; c < 32; c++) {
            const float* wpr = Wp + (size_t)(g*32 + c)*CIN;
            const float* wgr = Wg + (size_t)(g*32 + c)*CIN;
            float wpi = wpr[i], wgi = wgr[i];
            m0 += wpi*wgr[tid]       + wgi*wpr[tid];
            m1 += wpi*wgr[tid + 256] + wgi*wpr[tid + 256];
        }
        __half* dst = g_M16 + ((size_t)g*CIN + i)*CIN;
        dst[tid]       = __float2half(0.5f*m0);
        dst[tid + 256] = __float2half(0.5f*m1);
    } else {
        // ===== prepC: one (g,i) row of Csym = Wt^T (Wz^T Wz) Wt (Q-form) =====
        const int idx = cta - NP_S - NP_X - NP_A - NP_M;
        const int g = idx >> 9, i = idx & 511;
        for (int q = tid; q < 2048; q += 256)
            sWz[q] = Wz[(size_t)g*2048 + q];
        __syncthreads();
        for (int p = tid; p < 1024; p += 256) {
            int c2 = p >> 5, d = p & 31;
            float q = 0.f;
#pragma unroll 8
            for (int o = 0; o < 64; o++)
                q += sWz[o*32 + c2] * sWz[o*32 + d];
            sQ[c2*33 + d] = q;
        }
        __syncthreads();
        if (tid < 32) {
            float v = 0.f;
#pragma unroll 8
            for (int c2 = 0; c2 < 32; c2++)
                v += Wt[(size_t)(g*32 + c2)*CIN + i] * sQ[c2*33 + tid];
            sV[tid] = v;
        }
        __syncthreads();
        float c0 = 0.f, c1 = 0.f;
#pragma unroll 8
        for (int d = 0; d < 32; d++) {
            const float* wtr = Wt + (size_t)(g*32 + d)*CIN;
            float vd = sV[d];
            c0 += vd * wtr[tid];
            c1 += vd * wtr[tid + 256];
        }
        __half* dst = g_C16 + ((size_t)g*CIN + i)*CIN;
        dst[tid]       = __float2half(c0);
        dst[tid + 256] = __float2half(c1);
    }
}

// ---------------- K2: contract S vs Msym (att) + Csym (sumsq); colsum tail ----------------
__global__ void k_att() {
    __shared__ float rb[128];
    const int cta = blockIdx.x;
    const int tid = threadIdx.x;

    if (cta >= 160) {
        // colsum of Wcomb (fp16-rounded, matching actual u)
        const int g = cta - 160;
        for (int k = tid; k < CIN; k += 256) {
            float s = 0.f;
#pragma unroll 8
            for (int o = 0; o < 64; o++)
                s += __half2float(g_A16[(size_t)(64*g + o)*CIN + k]);
            g_colsum[g*CIN + k] = s;
        }
        return;
    }

    const int pr = cta % NPAIR, b = cta / NPAIR;
    int ib = 0, rem = pr;
    while (rem > ib) { rem -= (ib + 1); ib++; }
    const int jb = rem;
    const float fac = (ib == jb) ? 1.f : 2.f;

    const int lane = tid & 31, warp = tid >> 5;
    const int r = tid >> 1, c0 = (tid & 1)*64;

    const __half* sp = g_S + ((size_t)(b*NPAIR + pr) << 14) + r*128 + c0;
    float sv[64];
#pragma unroll
    for (int q = 0; q < 8; q++) {
        uint4 v = *(const uint4*)(sp + q*8);
        const __half2* h = (const __half2*)&v;
#pragma unroll
        for (int p = 0; p < 4; p++) {
            float2 f = __half22float2(h[p]);
            sv[q*8 + p*2]     = f.x;
            sv[q*8 + p*2 + 1] = f.y;
        }
    }

    for (int g = 0; g < G_; g++) {
        const size_t moff = ((size_t)g*CIN + ib*128 + r)*CIN + jb*128 + c0;
        const __half* mp = g_M16 + moff;
        const __half* cp = g_C16 + moff;
        float a = 0.f, ss = 0.f;
#pragma unroll
        for (int q = 0; q < 8; q++) {
            uint4 mv = *(const uint4*)(mp + q*8);
            uint4 cv = *(const uint4*)(cp + q*8);
            const __half2* mh = (const __half2*)&mv;
            const __half2* ch = (const __half2*)&cv;
#pragma unroll
            for (int p = 0; p < 4; p++) {
                float2 mf = __half22float2(mh[p]);
                float2 cf = __half22float2(ch[p]);
                a  += sv[q*8 + p*2]*mf.x + sv[q*8 + p*2 + 1]*mf.y;
                ss += sv[q*8 + p*2]*cf.x + sv[q*8 + p*2 + 1]*cf.y;
            }
        }
        a = wred(a); ss = wred(ss);
        if (lane == 0) { rb[g*8 + warp] = a; rb[64 + g*8 + warp] = ss; }
    }
    __syncthreads();
    if (tid < G_) {
        float a = 0.f;
#pragma unroll
        for (int w2 = 0; w2 < 8; w2++) a += rb[tid*8 + w2];
        g_attp[(b*G_ + tid)*NPAIR + pr] = a * fac;
    } else if (tid >= 64 && tid < 64 + G_) {
        int g = tid - 64;
        float s = 0.f;
#pragma unroll
        for (int w2 = 0; w2 < 8; w2++) s += rb[64 + g*8 + w2];
        g_ssp[(b*G_ + g)*NPAIR + pr] = s * fac;
    }
}

// ---------------- K3: fold att + analytic GN stats into per-(b,c) scale/bias ----------------
__global__ void k_stats(const float* __restrict__ gamma, const float* __restrict__ beta) {
    const int b = blockIdx.x, tid = threadIdx.x;
    const int w = tid >> 5, lane = tid & 31;
    __shared__ float sS[8], sMu[8];
    float at = (lane < NPAIR) ? g_attp[(b*G_ + w)*NPAIR + lane] : 0.f;
    float ss = (lane < NPAIR) ? g_ssp[(b*G_ + w)*NPAIR + lane] : 0.f;
    float mp = 0.f;
#pragma unroll
    for (int q = 0; q < 16; q++)
        mp += g_colsum[w*CIN + lane*16 + q] * g_xsum[b*CIN + lane*16 + q];
    at = wred(at); ss = wred(ss); mp = wred(mp);
    if (lane == 0) {
        const float n = 64.0f * 4096.0f;
        float mu  = mp / n;
        float var = fmaxf(ss / n - mu*mu, 0.f);
        float rstd = rsqrtf(at*at*var + EPSG);
        sS[w]  = at * rstd;
        sMu[w] = mu;
    }
    __syncthreads();
#pragma unroll
    for (int q = 0; q < 2; q++) {
        int c = tid + q*256;
        int g = c >> 6;
        float S = sS[g], mu = sMu[g];
        g_scale[b*CIN + c] = S * gamma[c];
        g_bias[b*CIN + c]  = beta[c] - S * mu * gamma[c];
    }
}

// ---------------- K4: u-GEMM with fused output epilogue (round-12 proven) ----------------
__global__ void __launch_bounds__(256, 2)
k_u(float* __restrict__ out) {
    extern __shared__ char smem[];
    const uint32_t sb = smem_u32(smem);
    __shared__ float s_sc[128], s_bi[128];

    const int tid  = threadIdx.x;
    const int lane = tid & 31, warp = tid >> 5;
    const int wm = warp >> 1, wn = warp & 1;
    const int cta = blockIdx.x;
    const int stile = cta & 31, yy = (cta >> 5) & 3, b = cta >> 7;
    const int scol0 = stile * 128;
    const int lr = lane >> 2, lc2 = (lane & 3)*2;

    const int arow = tid >> 1, ah = tid & 1;
    const __half* asrc = g_A16 + ((size_t)yy*128 + arow)*CIN + ah*16;
    const uint32_t adst = sb + arow*80 + ah*32;
    const int bk = (tid >> 4), bn16 = tid & 15;
    const __half* bsrc0 = g_x16 + ((size_t)b*CIN + bk)*HW + scol0 + bn16*8;
    const uint32_t bdst = sb + A_STG + bk*272 + bn16*16;

    auto issue = [&](int s) {
        if (s < 16) {
            const int st = (s & 3)*STG_U;
            cpasync16(adst + st,          asrc + s*32);
            cpasync16(adst + st + 16,     asrc + s*32 + 8);
            cpasync16(bdst + st,          bsrc0 + (size_t)s*32*HW);
            cpasync16(bdst + st + 16*272, bsrc0 + (size_t)(s*32 + 16)*HW);
        }
        CP_COMMIT();
    };

    const int a_row = wm*32 + (lane & 15);
    const int a_kw  = (lane >> 4) * 4;
    const int b_k   = lane & 15;
    const int b_w   = (lane >> 4) * 4;

    float acc[2][8][4];
#pragma unroll
    for (int mt = 0; mt < 2; mt++)
#pragma unroll
        for (int nt = 0; nt < 8; nt++)
#pragma unroll
            for (int i = 0; i < 4; i++) acc[mt][nt][i] = 0.f;

    if (tid < 128) {
        s_sc[tid] = g_scale[b*CIN + yy*128 + tid];
        s_bi[tid] = g_bias[b*CIN + yy*128 + tid];
    }

    issue(0);
    issue(1);
    for (int s = 0; s < 16; s++) {
        issue(s + 2);
        CP_WAIT(2);
        __syncthreads();
        const uint32_t abuf = sb + (s & 3)*STG_U;
        const uint32_t bbuf = abuf + A_STG;
#pragma unroll
        for (int ks = 0; ks < 2; ks++) {
            unsigned af[2][4], bf[4][4];
#pragma unroll
            for (int mt = 0; mt < 2; mt++)
                ldsm4(af[mt], abuf + ((a_row + mt*16)*AS_LD + ks*8 + a_kw)*4);
#pragma unroll
            for (int ng = 0; ng < 4; ng++)
                ldsm4t(bf[ng], bbuf + ((ks*16 + b_k)*BS_LD + wn*32 + ng*8 + b_w)*4);
#pragma unroll
            for (int mt = 0; mt < 2; mt++)
#pragma unroll
                for (int ng = 0; ng < 4; ng++) {
                    mma16(acc[mt][2*ng],     af[mt], &bf[ng][0]);
                    mma16(acc[mt][2*ng + 1], af[mt], &bf[ng][2]);
                }
        }
    }
    CP_WAIT(0);
    __syncthreads();

    // fused epilogue: out = scale*u + bias + x
#pragma unroll
    for (int mt = 0; mt < 2; mt++)
#pragma unroll
        for (int nt = 0; nt < 8; nt++)
#pragma unroll
            for (int i2 = 0; i2 < 2; i2++) {
                int rloc = wm*32 + mt*16 + lr + i2*8;
                int ccol = wn*64 + nt*8 + lc2;
                float sc = s_sc[rloc], bi = s_bi[rloc];
                size_t off = ((size_t)b*CIN + yy*128 + rloc)*HW + scol0 + ccol;
                float2 xf = __half22float2(*(const __half2*)&g_x16[off]);
                float2 o;
                o.x = fmaf(sc, acc[mt][nt][i2*2],     bi + xf.x);
                o.y = fmaf(sc, acc[mt][nt][i2*2 + 1], bi + xf.y);
                *(float2*)&out[off] = o;
            }
}

// ---------------- launch ----------------
extern "C" void kernel_launch(void* const* d_in, const int* in_sizes, int n_in,
                              void* d_out, int out_size) {
    const float* x     = (const float*)d_in[0];
    const float* Wt    = (const float*)d_in[1];
    const float* Wp    = (const float*)d_in[2];
    const float* Wg    = (const float*)d_in[3];
    const float* Wz    = (const float*)d_in[4];
    const float* gamma = (const float*)d_in[5];
    const float* beta  = (const float*)d_in[6];
    float* out = (float*)d_out;

    cudaFuncSetAttribute(k_prep, cudaFuncAttributeMaxDynamicSharedMemorySize, SMEM_P);
    cudaFuncSetAttribute(k_u,    cudaFuncAttributeMaxDynamicSharedMemorySize, SMEM_U);

    k_prep<<<NP_TOT, 256, SMEM_P>>>(x, Wt, Wz, Wp, Wg);
    k_att<<<168, 256>>>();
    k_stats<<<B_, 256>>>(gamma, beta);
    k_u<<<2048, 256, SMEM_U>>>(out);     // 4th launch -> profiled
}

// round 15
// speedup vs baseline: 1.6052x; 1.6052x over previous
#include <cuda_runtime.h>
#include <cuda_fp16.h>
#include <cstdint>
#include <cstddef>

// Problem constants
#define B_   16
#define CIN  512
#define HW   4096
#define G_   8
#define EPSG 1e-5f
#define STILES 32           // HW / 128

// GEMM: CTA tile M=128, N=128, K=512, k-stage 32, 4-deep cp.async ring, 2 CTA/SM
#define AS_LD 20            // A k-row stride in words (16 data + 4 pad)
#define BS_LD 68            // B k-row stride in words (64 data + 4 pad)
#define A_STG 10240         // 128 rows * 80 B
#define B_STG 8704          // 32 k-rows * 272 B
#define STG   18944
#define SMEM_GEMM (4*STG)   // 75776 -> 2 CTAs/SM
#define DMP_LD 130          // att g-dump row stride (floats), even

// merged prep grid
#define NPX 32768           // prepX CTAs (256 float4 each)
#define NPA 1024            // prepA CTAs (one g_AW row each)

// ---------------- device scratch ----------------
// rows 0..511: Wcomb ; rows 512..1023: 4 chunks of [Wp(64);Wg(64)]
__device__ __half g_AW[1024*CIN];
__device__ __half g_x16[(size_t)B_*CIN*HW];      // x fp16 (67 MB)
__device__ __half g_u[(size_t)B_*CIN*HW];        // u fp16 (67 MB)
__device__ float  g_attp[B_*G_*STILES];
__device__ float  g_sump[B_*G_*STILES];
__device__ float  g_sumsqp[B_*G_*STILES];
__device__ float  g_scale[B_*CIN];
__device__ float  g_bias[B_*CIN];

// ---------------- PTX helpers ----------------
__device__ __forceinline__ uint32_t smem_u32(const void* p) {
    uint32_t a;
    asm("{ .reg .u64 t; cvta.to.shared.u64 t, %1; cvt.u32.u64 %0, t; }" : "=r"(a) : "l"(p));
    return a;
}
__device__ __forceinline__ void cpasync16(uint32_t dst, const void* src) {
    asm volatile("cp.async.cg.shared.global [%0], [%1], 16;" :: "r"(dst), "l"(src) : "memory");
}
#define CP_COMMIT()  asm volatile("cp.async.commit_group;" ::: "memory")
#define CP_WAIT(n)   asm volatile("cp.async.wait_group %0;" :: "n"(n) : "memory")

__device__ __forceinline__ void ldsm4(unsigned* r, uint32_t a) {
    asm volatile("ldmatrix.sync.aligned.m8n8.x4.shared.b16 {%0,%1,%2,%3}, [%4];"
        : "=r"(r[0]), "=r"(r[1]), "=r"(r[2]), "=r"(r[3]) : "r"(a));
}
__device__ __forceinline__ void ldsm4t(unsigned* r, uint32_t a) {
    asm volatile("ldmatrix.sync.aligned.m8n8.x4.trans.shared.b16 {%0,%1,%2,%3}, [%4];"
        : "=r"(r[0]), "=r"(r[1]), "=r"(r[2]), "=r"(r[3]) : "r"(a));
}
__device__ __forceinline__ void mma16(float* c, const unsigned* a, const unsigned* b) {
    asm volatile(
        "mma.sync.aligned.m16n8k16.row.col.f32.f16.f16.f32 "
        "{%0,%1,%2,%3}, {%4,%5,%6,%7}, {%8,%9}, {%0,%1,%2,%3};\n"
        : "+f"(c[0]), "+f"(c[1]), "+f"(c[2]), "+f"(c[3])
        : "r"(a[0]), "r"(a[1]), "r"(a[2]), "r"(a[3]), "r"(b[0]), "r"(b[1]));
}
__device__ __forceinline__ float wred(float v) {
#pragma unroll
    for (int o = 16; o; o >>= 1) v += __shfl_down_sync(0xffffffffu, v, o);
    return v;
}

// ---------------- K1: merged prep (prepX | prepA), one launch ----------------
__global__ void k_prep(const float* __restrict__ x,  const float* __restrict__ Wt,
                       const float* __restrict__ Wz, const float* __restrict__ Wp,
                       const float* __restrict__ Wg) {
    const int cta = blockIdx.x;
    const int tid = threadIdx.x;

    if (cta < NPX) {
        // ----- prepX: 256 float4 -> fp16 -----
        size_t i = (size_t)cta * 256 + tid;
        float4 v = ((const float4*)x)[i];
        __half2* d = (__half2*)g_x16;
        d[2*i]     = __floats2half2_rn(v.x, v.y);
        d[2*i + 1] = __floats2half2_rn(v.z, v.w);
    } else {
        // ----- prepA: one g_AW row -----
        const int r = cta - NPX;          // 0..1023
        __half* dst = g_AW + (size_t)r*CIN;
        if (r < 512) {
            int g = r >> 6, o = r & 63;
            __shared__ float wz[32];
            if (tid < 32) wz[tid] = Wz[(size_t)(g*64 + o)*32 + tid];
            __syncthreads();
#pragma unroll
            for (int q = 0; q < 2; q++) {
                int i = tid + q*256;
                float a = 0.f;
#pragma unroll 8
                for (int c = 0; c < 32; c++)
                    a += wz[c] * Wt[(size_t)(g*32 + c)*CIN + i];
                dst[i] = __float2half(a);
            }
        } else {
            int idx = r - 512;
            int chunk = idx >> 7, row = idx & 127;
            const float* src = (row < 64) ? Wp + (size_t)(chunk*64 + row)*CIN
                                          : Wg + (size_t)(chunk*64 + row - 64)*CIN;
#pragma unroll
            for (int q = 0; q < 2; q++) {
                int i = tid + q*256;
                dst[i] = __float2half(src[i]);
            }
        }
    }
}

// ---------------- K2: unified GEMM (round-7 proven) ----------------
// yy<4: C = Wcomb[yy*128..] @ X  -> u + GN partials
// yy>=4: C = [Wp;Wg](chunk yy-4) @ X -> att partials
__global__ void __launch_bounds__(256, 2)
k_gemm() {
    extern __shared__ char smem[];
    const uint32_t sb = smem_u32(smem);
    __shared__ float rbuf[16];

    const int tid  = threadIdx.x;
    const int lane = tid & 31, warp = tid >> 5;
    const int wm = warp >> 1, wn = warp & 1;     // 4m x 2n warps; warp tile 32m x 64n
    const int stile = blockIdx.x, yy = blockIdx.y, b = blockIdx.z;
    const int scol0 = stile * 128;

    // cp.async loaders
    const int arow = tid >> 1, ah = tid & 1;     // A: 2 chunks/thread
    const __half* asrc = g_AW + ((size_t)yy*128 + arow)*CIN + ah*16;
    const uint32_t adst = sb + arow*80 + ah*32;
    const int bk = (tid >> 4), bn16 = tid & 15;  // B: 2 chunks/thread
    const __half* bsrc0 = g_x16 + ((size_t)b*CIN + bk)*HW + scol0 + bn16*8;
    const uint32_t bdst = sb + A_STG + bk*272 + bn16*16;

    auto issue = [&](int s) {
        if (s < 16) {
            const int st = (s & 3)*STG;
            cpasync16(adst + st,      asrc + s*32);
            cpasync16(adst + st + 16, asrc + s*32 + 8);
            cpasync16(bdst + st,            bsrc0 + (size_t)s*32*HW);
            cpasync16(bdst + st + 16*272,   bsrc0 + (size_t)(s*32 + 16)*HW);
        }
        CP_COMMIT();
    };

    const int a_row = wm*32 + (lane & 15);
    const int a_kw  = (lane >> 4) * 4;
    const int b_k   = lane & 15;
    const int b_w   = (lane >> 4) * 4;

    float acc[2][8][4];
#pragma unroll
    for (int mt = 0; mt < 2; mt++)
#pragma unroll
        for (int nt = 0; nt < 8; nt++)
#pragma unroll
            for (int i = 0; i < 4; i++) acc[mt][nt][i] = 0.f;

    issue(0);
    issue(1);

    for (int s = 0; s < 16; s++) {
        issue(s + 2);
        CP_WAIT(2);
        __syncthreads();
        const uint32_t abuf = sb + (s & 3)*STG;
        const uint32_t bbuf = abuf + A_STG;
#pragma unroll
        for (int ks = 0; ks < 2; ks++) {
            unsigned af[2][4], bf[4][4];
#pragma unroll
            for (int mt = 0; mt < 2; mt++)
                ldsm4(af[mt], abuf + ((a_row + mt*16)*AS_LD + ks*8 + a_kw)*4);
#pragma unroll
            for (int ng = 0; ng < 4; ng++)
                ldsm4t(bf[ng], bbuf + ((ks*16 + b_k)*BS_LD + wn*32 + ng*8 + b_w)*4);
#pragma unroll
            for (int mt = 0; mt < 2; mt++)
#pragma unroll
                for (int ng = 0; ng < 4; ng++) {
                    mma16(acc[mt][2*ng],     af[mt], &bf[ng][0]);
                    mma16(acc[mt][2*ng + 1], af[mt], &bf[ng][2]);
                }
        }
    }
    CP_WAIT(0);
    __syncthreads();

    const int lr = lane >> 2, lc2 = (lane & 3)*2;

    if (yy < 4) {
        // ---- u epilogue: channels yy*128 + wm*32 + ... ; GN group = yy*2 + (wm>>1) ----
        float s1 = 0.f, s2 = 0.f;
        const size_t ub = ((size_t)b*CIN + yy*128 + wm*32)*HW + scol0 + wn*64;
#pragma unroll
        for (int mt = 0; mt < 2; mt++)
#pragma unroll
            for (int nt = 0; nt < 8; nt++)
#pragma unroll
                for (int i2 = 0; i2 < 2; i2++) {
                    float v0 = acc[mt][nt][i2*2], v1 = acc[mt][nt][i2*2 + 1];
                    int r = mt*16 + lr + i2*8;
                    int c = nt*8 + lc2;
                    *(__half2*)&g_u[ub + (size_t)r*HW + c] = __floats2half2_rn(v0, v1);
                    s1 += v0 + v1;
                    s2 += v0*v0 + v1*v1;
                }
        s1 = wred(s1); s2 = wred(s2);
        if (lane == 0) { rbuf[warp] = s1; rbuf[8 + warp] = s2; }
        __syncthreads();
        if (tid < 2) {
            int g = yy*2 + tid;
            float ss = rbuf[tid*4] + rbuf[tid*4+1] + rbuf[tid*4+2] + rbuf[tid*4+3];
            float qq = rbuf[8+tid*4] + rbuf[8+tid*4+1] + rbuf[8+tid*4+2] + rbuf[8+tid*4+3];
            g_sump[(b*G_ + g)*STILES + stile]   = ss;
            g_sumsqp[(b*G_ + g)*STILES + stile] = qq;
        }
    } else {
        // ---- att epilogue: rows 0-63 = p, 64-127 = g ; pair warp wm <-> wm+2 ----
        const int yc = yy - 4;
        float* dmp = (float*)smem;   // [64][DMP_LD]
        if (wm >= 2) {
#pragma unroll
            for (int mt = 0; mt < 2; mt++)
#pragma unroll
                for (int nt = 0; nt < 8; nt++)
#pragma unroll
                    for (int i2 = 0; i2 < 2; i2++) {
                        int r = (wm - 2)*32 + mt*16 + lr + i2*8;
                        int c = wn*64 + nt*8 + lc2;
                        *(float2*)&dmp[r*DMP_LD + c] =
                            make_float2(acc[mt][nt][i2*2], acc[mt][nt][i2*2+1]);
                    }
        }
        __syncthreads();
        if (wm < 2) {
            float pg = 0.f;
#pragma unroll
            for (int mt = 0; mt < 2; mt++)
#pragma unroll
                for (int nt = 0; nt < 8; nt++)
#pragma unroll
                    for (int i2 = 0; i2 < 2; i2++) {
                        int r = wm*32 + mt*16 + lr + i2*8;
                        int c = wn*64 + nt*8 + lc2;
                        pg += acc[mt][nt][i2*2]     * dmp[r*DMP_LD + c]
                            + acc[mt][nt][i2*2 + 1] * dmp[r*DMP_LD + c + 1];
                    }
            pg = wred(pg);
            if (lane == 0) rbuf[warp] = pg;
        }
        __syncthreads();
        if (tid < 2) {
            float a = rbuf[tid*2] + rbuf[tid*2 + 1];
            g_attp[(b*G_ + yc*2 + tid)*STILES + stile] = a;
        }
    }
}

// ---------------- K3: fold att + GN into per-(b,c) scale/bias ----------------
__global__ void k_stats(const float* __restrict__ gamma, const float* __restrict__ beta) {
    const int b = blockIdx.x, tid = threadIdx.x;
    const int w = tid >> 5, lane = tid & 31;
    __shared__ float sS[8], sMu[8];
    float sm = g_sump[(b*G_ + w)*STILES + lane];
    float sq = g_sumsqp[(b*G_ + w)*STILES + lane];
    float at = g_attp[(b*G_ + w)*STILES + lane];
    sm = wred(sm); sq = wred(sq); at = wred(at);
    if (lane == 0) {
        const float n = 64.0f * 4096.0f;
        float mu  = sm / n;
        float var = fmaxf(sq / n - mu*mu, 0.f);
        float rstd = rsqrtf(at*at*var + EPSG);
        sS[w]  = at * rstd;
        sMu[w] = mu;
    }
    __syncthreads();
#pragma unroll
    for (int q = 0; q < 2; q++) {
        int c = tid + q*256;
        int g = c >> 6;
        float S = sS[g], mu = sMu[g];
        g_scale[b*CIN + c] = S * gamma[c];
        g_bias[b*CIN + c]  = beta[c] - S * mu * gamma[c];
    }
}

// ---------------- K4: out = scale*u + bias + x (x from fp16) ----------------
__global__ void k_final(float* __restrict__ out) {
    size_t i = (size_t)blockIdx.x * blockDim.x + threadIdx.x;   // float4 index
    size_t e = i << 2;
    int b = (int)(e >> 21);
    int c = (int)((e >> 12) & 511);
    float sc = g_scale[b*CIN + c];
    float bi = g_bias[b*CIN + c];
    const __half2* up = (const __half2*)g_u;
    const __half2* xp = (const __half2*)g_x16;
    float2 u0 = __half22float2(up[2*i]);
    float2 u1 = __half22float2(up[2*i + 1]);
    float2 x0 = __half22float2(xp[2*i]);
    float2 x1 = __half22float2(xp[2*i + 1]);
    float4 o;
    o.x = fmaf(sc, u0.x, bi + x0.x);
    o.y = fmaf(sc, u0.y, bi + x0.y);
    o.z = fmaf(sc, u1.x, bi + x1.x);
    o.w = fmaf(sc, u1.y, bi + x1.y);
    ((float4*)out)[i] = o;
}

// ---------------- launch ----------------
extern "C" void kernel_launch(void* const* d_in, const int* in_sizes, int n_in,
                              void* d_out, int out_size) {
    const float* x     = (const float*)d_in[0];
    const float* Wt    = (const float*)d_in[1];
    const float* Wp    = (const float*)d_in[2];
    const float* Wg    = (const float*)d_in[3];
    const float* Wz    = (const float*)d_in[4];
    const float* gamma = (const float*)d_in[5];
    const float* beta  = (const float*)d_in[6];
    float* out = (float*)d_out;

    cudaFuncSetAttribute(k_gemm, cudaFuncAttributeMaxDynamicSharedMemorySize, SMEM_GEMM);

    k_prep<<<NPX + NPA, 256>>>(x, Wt, Wz, Wp, Wg);
    k_gemm<<<dim3(STILES, 8, B_), 256, SMEM_GEMM>>>();
    k_stats<<<B_, 256>>>(gamma, beta);
    k_final<<<32768, 256>>>(out);
}